// round 4
// baseline (speedup 1.0000x reference)
#include <cuda_runtime.h>
#include <math.h>

#define BB   8
#define NN   2048
#define KK   16
#define CIN  128
#define HID  128
#define COUT 128
#define NNODE (BB * NN)
#define PN   8     // nodes per block in precompute

// scratch: per-node projections  A = h@(W1a-W1b)+b1,  U = h@W1b
__device__ float g_A[NNODE * HID];
__device__ float g_U[NNODE * HID];
// W2 interleaved for f32x2: index (dd*COUT + c)*2 + j holds pack(W2[4dd+2j][c], W2[4dd+2j+1][c])
__device__ unsigned long long g_W2p[(HID / 4) * COUT * 2];
__device__ int g_idx_is64;

// ---- f32x2 packed-math helpers (FFMA2 path, ptxas never emits from C++) ----
__device__ __forceinline__ unsigned long long ffma2(unsigned long long a,
                                                    unsigned long long b,
                                                    unsigned long long c) {
    unsigned long long d;
    asm("fma.rn.f32x2 %0, %1, %2, %3;" : "=l"(d) : "l"(a), "l"(b), "l"(c));
    return d;
}
__device__ __forceinline__ unsigned long long pack2(float lo, float hi) {
    unsigned long long v;
    asm("mov.b64 %0, {%1, %2};" : "=l"(v) : "f"(lo), "f"(hi));
    return v;
}
__device__ __forceinline__ float2 unpack2(unsigned long long v) {
    float2 r;
    asm("mov.b64 {%0, %1}, %2;" : "=f"(r.x), "=f"(r.y) : "l"(v));
    return r;
}

__global__ void detect_idx_kernel(const int* __restrict__ idx_raw) {
    if (threadIdx.x < 32) {
        int nz = (idx_raw[2 * threadIdx.x + 1] != 0) |
                 (idx_raw[2 * (threadIdx.x + 32) + 1] != 0);
        unsigned m = __ballot_sync(0xffffffffu, nz);
        if (threadIdx.x == 0) g_idx_is64 = (m == 0u);
    }
}

__global__ void prepack_kernel(const float* __restrict__ W2) {
    const int i = blockIdx.x * blockDim.x + threadIdx.x;   // 0..8191
    const int j  = i & 1;
    const int c  = (i >> 1) & (COUT - 1);
    const int dd = i >> 8;
    const int d  = 4 * dd + 2 * j;
    g_W2p[i] = pack2(W2[d * COUT + c], W2[(d + 1) * COUT + c]);
}

__device__ __forceinline__ float gelu_exact(float x) {
    return 0.5f * x * (1.0f + erff(x * 0.70710678118654752440f));
}

// ---------------------------------------------------------------------------
// Precompute A = h@(W1a-W1b)+b1,  U = h@W1b   (f32x2 packed along d)
// ---------------------------------------------------------------------------
__global__ __launch_bounds__(128) void precompute_kernel(
    const float* __restrict__ h,   // (NNODE, CIN)
    const float* __restrict__ W1,  // (259, HID)
    const float* __restrict__ b1)  // (HID)
{
    __shared__ float hs[PN][CIN];
    const int t     = threadIdx.x;
    const int node0 = blockIdx.x * PN;

    #pragma unroll
    for (int i = 0; i < PN; ++i)
        hs[i][t] = h[(size_t)(node0 + i) * CIN + t];
    __syncthreads();

    unsigned long long accA[PN], accU[PN];
    #pragma unroll
    for (int i = 0; i < PN; ++i) { accA[i] = 0ull; accU[i] = 0ull; }

    #pragma unroll 2
    for (int dd = 0; dd < CIN / 4; ++dd) {
        const int d0 = 4 * dd;
        float w1a[4], w1b[4];
        #pragma unroll
        for (int j = 0; j < 4; ++j) {
            w1a[j] = W1[(d0 + j) * HID + t];
            w1b[j] = W1[(CIN + d0 + j) * HID + t];
        }
        const unsigned long long wa01 = pack2(w1a[0] - w1b[0], w1a[1] - w1b[1]);
        const unsigned long long wa23 = pack2(w1a[2] - w1b[2], w1a[3] - w1b[3]);
        const unsigned long long wb01 = pack2(w1b[0], w1b[1]);
        const unsigned long long wb23 = pack2(w1b[2], w1b[3]);
        #pragma unroll
        for (int i = 0; i < PN; ++i) {
            const ulonglong2 m2 = *reinterpret_cast<const ulonglong2*>(&hs[i][d0]);
            accA[i] = ffma2(m2.x, wa01, accA[i]);
            accA[i] = ffma2(m2.y, wa23, accA[i]);
            accU[i] = ffma2(m2.x, wb01, accU[i]);
            accU[i] = ffma2(m2.y, wb23, accU[i]);
        }
    }
    const float bv = b1[t];
    #pragma unroll
    for (int i = 0; i < PN; ++i) {
        const float2 a2 = unpack2(accA[i]);
        const float2 u2 = unpack2(accU[i]);
        g_A[(size_t)(node0 + i) * HID + t] = a2.x + a2.y + bv;
        g_U[(size_t)(node0 + i) * HID + t] = u2.x + u2.y;
    }
}

// ---------------------------------------------------------------------------
// Main per-node kernel
// ---------------------------------------------------------------------------
__global__ __launch_bounds__(128) void edgeconv_kernel(
    const float* __restrict__ pos,
    const int*   __restrict__ idx_raw,
    const float* __restrict__ W1,      // rows 256..258 (rel weights)
    const float* __restrict__ b2,
    const float* __restrict__ gamma,
    const float* __restrict__ beta,
    float*       __restrict__ out)
{
    __shared__ int   jidx[KK];
    __shared__ float rel_s[KK][4];
    __shared__ float x1_s[KK][HID];
    __shared__ float pmax[2][COUT];
    __shared__ float red_s[4];

    const int t    = threadIdx.x;
    const int node = blockIdx.x;
    const int b    = node >> 11;
    const int n    = node & (NN - 1);
    const float* pb = pos + (size_t)b * NN * 3;

    if (t < KK) {
        const int is64 = g_idx_is64;
        long e = (long)node * KK + t;
        jidx[t] = is64 ? idx_raw[2 * e] : idx_raw[e];
    }
    __syncthreads();

    if (t < 3 * KK) {
        const int k = t / 3, c = t - 3 * k;
        rel_s[k][c] = pb[jidx[k] * 3 + c] - pb[n * 3 + c];
    }

    const float a   = g_A[(size_t)node * HID + t];
    const float wc0 = W1[(2 * CIN + 0) * HID + t];
    const float wc1 = W1[(2 * CIN + 1) * HID + t];
    const float wc2 = W1[(2 * CIN + 2) * HID + t];
    float uk[KK];
    #pragma unroll
    for (int k = 0; k < KK; ++k)
        uk[k] = g_U[((size_t)b * NN + jidx[k]) * HID + t];
    __syncthreads();

    #pragma unroll
    for (int k = 0; k < KK; ++k) {
        float v = a + uk[k];
        v = fmaf(rel_s[k][0], wc0, v);
        v = fmaf(rel_s[k][1], wc1, v);
        v = fmaf(rel_s[k][2], wc2, v);
        x1_s[k][t] = gelu_exact(v);
    }
    __syncthreads();

    // ---- GEMM2, 2 cols x 8 k per thread, f32x2 packed along d ----
    const int half  = t >> 6;       // 0: k=0..7, 1: k=8..15
    const int u     = t & 63;
    const int c0    = 2 * u;
    const int kbase = half * 8;

    unsigned long long acc0[8], acc1[8];
    #pragma unroll
    for (int i = 0; i < 8; ++i) { acc0[i] = 0ull; acc1[i] = 0ull; }

    #pragma unroll 2
    for (int dd = 0; dd < HID / 4; ++dd) {
        const int d0 = 4 * dd;
        const ulonglong2 wA = *reinterpret_cast<const ulonglong2*>(&g_W2p[(dd * COUT + c0) * 2]);
        const ulonglong2 wB = *reinterpret_cast<const ulonglong2*>(&g_W2p[(dd * COUT + c0 + 1) * 2]);
        #pragma unroll
        for (int kk = 0; kk < 8; ++kk) {
            const ulonglong2 m2 = *reinterpret_cast<const ulonglong2*>(&x1_s[kbase + kk][d0]);
            acc0[kk] = ffma2(m2.x, wA.x, acc0[kk]);
            acc0[kk] = ffma2(m2.y, wA.y, acc0[kk]);
            acc1[kk] = ffma2(m2.x, wB.x, acc1[kk]);
            acc1[kk] = ffma2(m2.y, wB.y, acc1[kk]);
        }
    }

    // horizontal add + bias + gelu + partial max
    const float2 bv2 = *reinterpret_cast<const float2*>(&b2[c0]);
    float v0 = -INFINITY, v1 = -INFINITY;
    #pragma unroll
    for (int kk = 0; kk < 8; ++kk) {
        const float2 p0 = unpack2(acc0[kk]);
        const float2 p1 = unpack2(acc1[kk]);
        v0 = fmaxf(v0, gelu_exact(p0.x + p0.y + bv2.x));
        v1 = fmaxf(v1, gelu_exact(p1.x + p1.y + bv2.y));
    }
    *reinterpret_cast<float2*>(&pmax[half][c0]) = make_float2(v0, v1);
    __syncthreads();

    const float v = fmaxf(pmax[0][t], pmax[1][t]);

    // ---- LayerNorm ----
    float s = v;
    #pragma unroll
    for (int o = 16; o > 0; o >>= 1) s += __shfl_xor_sync(0xffffffffu, s, o);
    if ((t & 31) == 0) red_s[t >> 5] = s;
    __syncthreads();
    const float mean = (red_s[0] + red_s[1] + red_s[2] + red_s[3]) * (1.0f / COUT);
    __syncthreads();

    const float dv = v - mean;
    float q = dv * dv;
    #pragma unroll
    for (int o = 16; o > 0; o >>= 1) q += __shfl_xor_sync(0xffffffffu, q, o);
    if ((t & 31) == 0) red_s[t >> 5] = q;
    __syncthreads();
    const float var = (red_s[0] + red_s[1] + red_s[2] + red_s[3]) * (1.0f / COUT);

    out[(size_t)node * COUT + t] = dv * rsqrtf(var + 1e-5f) * gamma[t] + beta[t];
}

extern "C" void kernel_launch(void* const* d_in, const int* in_sizes, int n_in,
                              void* d_out, int out_size) {
    const float* h     = (const float*)d_in[0];
    const float* pos   = (const float*)d_in[1];
    const int*   idx   = (const int*)  d_in[2];
    const float* W1    = (const float*)d_in[3];
    const float* b1    = (const float*)d_in[4];
    const float* W2    = (const float*)d_in[5];
    const float* b2    = (const float*)d_in[6];
    const float* gamma = (const float*)d_in[7];
    const float* beta  = (const float*)d_in[8];
    float*       out   = (float*)d_out;

    detect_idx_kernel<<<1, 32>>>(idx);
    prepack_kernel<<<32, 256>>>(W2);
    precompute_kernel<<<NNODE / PN, 128>>>(h, W1, b1);
    edgeconv_kernel<<<NNODE, 128>>>(pos, idx, W1, b2, gamma, beta, out);
}